// round 17
// baseline (speedup 1.0000x reference)
#include <cuda_runtime.h>

// ============================================================================
// GeneratorQuantumCircuit: 4-qubit state-vector sim.
// R16: TWO elements per thread, straight-line. Both LDG.128 issued up front
// (MLP=2) and both elements' MUFU tangent regions computed before either
// circuit runs -> halves the exposed ~577cyc DRAM stall per element that was
// keeping the fma pipe at 60%. Circuits run sequentially so register live
// range stays ~1 element; occupancy pinned at 5 CTAs/SM.
//
// Core (validated R11-R15): tangent gate algebra [[1,-t],[t,1]] with
// self-normalization; init amp(i) = (-i)^popcount(i) * prod t_w as sign-folded
// monomials; RY = 2 fma2/pair; CNOT = register rename; packed f32x2 epilogue.
// ============================================================================

typedef unsigned long long u64;

// ---- packed f32x2 helpers (Blackwell sm_100+) ------------------------------

__device__ __forceinline__ u64 pk2(float lo, float hi) {
    u64 r; asm("mov.b64 %0, {%1, %2};" : "=l"(r) : "f"(lo), "f"(hi)); return r;
}
__device__ __forceinline__ void unpk2(u64 v, float& lo, float& hi) {
    asm("mov.b64 {%0, %1}, %2;" : "=f"(lo), "=f"(hi) : "l"(v));
}
__device__ __forceinline__ u64 mul2(u64 a, u64 b) {
    u64 r; asm("mul.rn.f32x2 %0, %1, %2;" : "=l"(r) : "l"(a), "l"(b)); return r;
}
__device__ __forceinline__ u64 add2(u64 a, u64 b) {
    u64 r; asm("add.rn.f32x2 %0, %1, %2;" : "=l"(r) : "l"(a), "l"(b)); return r;
}
__device__ __forceinline__ u64 fma2(u64 a, u64 b, u64 c) {
    u64 r; asm("fma.rn.f32x2 %0, %1, %2, %3;" : "=l"(r) : "l"(a), "l"(b), "l"(c)); return r;
}
__device__ __forceinline__ float hadd2(u64 v) {
    float lo, hi; unpk2(v, lo, hi); return lo + hi;
}

// fast tangent: MUFU sin/cos + MUFU-rcp divide; no slow-path code region
__device__ __forceinline__ float fast_tan_half(float x) {
    float s, c;
    __sincosf(0.5f * x, &s, &c);
    return __fdividef(s, c);
}

// CNOT(ctrl C, tgt T): pure register permutation when fully unrolled.
template <int C, int T>
__device__ __forceinline__ void cnot(u64* a) {
#pragma unroll
    for (int i = 0; i < 16; i++) {
        if ((i & (1 << C)) && !(i & (1 << T))) {
            u64 t = a[i];
            a[i] = a[i | (1 << T)];
            a[i | (1 << T)] = t;
        }
    }
}

// Full circuit for one element given noise tangents + weight tangents.
__device__ __forceinline__ float4 run_circuit(float t0, float t1, float t2,
                                              float t3, const float* wt) {
    // ---- product state: amp(i) = (-i)^popcount(i) * prod_{w in i} t_w ------
    float g1 = -t0;
    float g2 = -t1;
    float g3 =  t1 * g1;
    float g4 = -t2;
    float g5 =  t2 * g1;
    float g6 =  t2 * g2;
    float g7 = -t2 * g3;
    float g8 = -t3;
    float g9 =  t3 * g1;
    float g10 = t3 * g2;
    float g11 = -t3 * g3;
    float g12 = t3 * g4;
    float g13 = -t3 * g5;
    float g14 = -t3 * g6;
    float g15 = t3 * g7;

    u64 a[16];
    a[0]  = pk2(1.f, 0.f);  a[1]  = pk2(0.f, g1);
    a[2]  = pk2(0.f, g2);   a[3]  = pk2(g3, 0.f);
    a[4]  = pk2(0.f, g4);   a[5]  = pk2(g5, 0.f);
    a[6]  = pk2(g6, 0.f);   a[7]  = pk2(0.f, g7);
    a[8]  = pk2(0.f, g8);   a[9]  = pk2(g9, 0.f);
    a[10] = pk2(g10, 0.f);  a[11] = pk2(0.f, g11);
    a[12] = pk2(g12, 0.f);  a[13] = pk2(0.f, g13);
    a[14] = pk2(0.f, g14);  a[15] = pk2(g15, 0.f);

    // ---- 2 layers: CNOT ring + RY (deferred cosine: [[1,-t],[t,1]]) --------
#pragma unroll
    for (int layer = 0; layer < 2; layer++) {
        cnot<0, 1>(a);
        cnot<1, 2>(a);
        cnot<2, 3>(a);
        cnot<3, 0>(a);

#pragma unroll
        for (int w = 0; w < 4; w++) {
            float tw = wt[layer * 4 + w];
            u64 tp = pk2(tw, tw);
            u64 tn = pk2(-tw, -tw);
            const int h = 1 << w;
#pragma unroll
            for (int i = 0; i < 16; i++) {
                if (i & h) continue;
                u64 a0 = a[i], a1 = a[i | h];
                a[i]     = fma2(tn, a1, a0);  // a0 - t*a1  (re & im together)
                a[i | h] = fma2(tp, a0, a1);  // a1 + t*a0
            }
        }
    }

    // ---- packed squares + marginals, then normalize by total ---------------
    u64 q[16];
#pragma unroll
    for (int i = 0; i < 16; i++) q[i] = mul2(a[i], a[i]);  // (re^2, im^2)

    u64 s01 = add2(q[0],  q[1]),  s23 = add2(q[2],  q[3]);
    u64 s45 = add2(q[4],  q[5]),  s67 = add2(q[6],  q[7]);
    u64 s89 = add2(q[8],  q[9]),  sab = add2(q[10], q[11]);
    u64 scd = add2(q[12], q[13]), sef = add2(q[14], q[15]);

    u64 A = add2(s01, s23);   // q0..q3
    u64 B = add2(s45, s67);   // q4..q7
    u64 C = add2(s89, sab);   // q8..q11
    u64 D = add2(scd, sef);   // q12..q15

    // wire0: even indices
    u64 E = add2(add2(add2(q[0], q[2]), add2(q[4],  q[6])),
                 add2(add2(q[8], q[10]), add2(q[12], q[14])));
    // wire1: {0,1,4,5,8,9,12,13}
    u64 Y = add2(add2(s01, s45), add2(s89, scd));

    u64 AB = add2(A, B);                    // wire 3 numerator (and half of T)
    float T = hadd2(add2(AB, add2(C, D)));  // total probability mass
    float r = __frcp_rn(T);                 // MUFU reciprocal (pipe is idle)

    float4 o;
    o.x = r * hadd2(E);            // wire 0
    o.y = r * hadd2(Y);            // wire 1
    o.z = r * hadd2(add2(A, C));   // wire 2
    o.w = r * hadd2(AB);           // wire 3
    return o;
}

__global__ void __launch_bounds__(256, 5)
qc_kernel(const float4* __restrict__ noise,
          const float*  __restrict__ weights,
          float4* __restrict__ out, int n) {
    __shared__ float wt_sh[8];

    // ---- per-block weight tangents: 8 fast-math tans, once per block -------
    if (threadIdx.x < 8) wt_sh[threadIdx.x] = fast_tan_half(weights[threadIdx.x]);
    __syncthreads();

    const int halfUp = (n + 1) >> 1;
    int g = blockIdx.x * blockDim.x + threadIdx.x;
    if (g >= halfUp) return;

    // ---- front-batch BOTH loads (MLP=2): coalesced pair (g, g+halfUp) ------
    int  e2   = g + halfUp;
    bool has2 = e2 < n;
    float4 nzA = noise[g];
    float4 nzB = noise[has2 ? e2 : g];

    float wt[8];
#pragma unroll
    for (int i = 0; i < 8; i++) wt[i] = wt_sh[i];   // LDS broadcast, N=1

    // ---- both elements' MUFU tangent regions up front (covers load B) ------
    float a0 = fast_tan_half(nzA.x);
    float a1 = fast_tan_half(nzA.y);
    float a2 = fast_tan_half(nzA.z);
    float a3 = fast_tan_half(nzA.w);
    float b0 = fast_tan_half(nzB.x);
    float b1 = fast_tan_half(nzB.y);
    float b2 = fast_tan_half(nzB.z);
    float b3 = fast_tan_half(nzB.w);

    // ---- run circuits sequentially (keeps register live-range small) -------
    out[g] = run_circuit(a0, a1, a2, a3, wt);
    float4 oB = run_circuit(b0, b1, b2, b3, wt);
    if (has2) out[e2] = oB;
}

extern "C" void kernel_launch(void* const* d_in, const int* in_sizes, int n_in,
                              void* d_out, int out_size) {
    const float* noise   = (const float*)d_in[0];   // (B, 4) f32
    const float* weights = (const float*)d_in[1];   // (2, 4) f32
    int B = in_sizes[0] / 4;

    int threads = 256;
    int pairs   = (B + 1) / 2;
    int blocks  = (pairs + threads - 1) / threads;
    qc_kernel<<<blocks, threads>>>((const float4*)noise, weights,
                                   (float4*)d_out, B);
}